// round 5
// baseline (speedup 1.0000x reference)
#include <cuda_runtime.h>
#include <cstdint>
#include <cstddef>
#include <math.h>

typedef unsigned long long ull;

#define BATCH 32
#define TT 4
#define NN 512
#define NROWS (BATCH * TT)  // 128
#define TL 64               // (k,l) tile edge
#define WT 132              // window floats per shift copy
#define NTILE 36            // upper-triangle 64x64 tiles (8x8 grid)

#define SMEM_WIN (8 * 4 * WT)        // 4224 floats
#define SMEM_KT  (3 * TT * TL * 2)   // 1536 floats (dup float2 tables)
#define SMEM_S   (2 * TL * 68)       // 8704 floats (mirror staging)
#define SMEM_BYTES ((SMEM_WIN + SMEM_KT + SMEM_S) * 4)   // 57856 B

// FFT results, SoA, duplicated to length 2N so (l-k)%N needs no mod.
__device__ float g_re[NROWS * 2 * NN];
__device__ float g_im[NROWS * 2 * NN];

// ---------------------------------------------------------------------------
// Kernel 1: 512-point complex FFT (Stockham autosort, radix-2), one row/block.
// ---------------------------------------------------------------------------
__global__ void __launch_bounds__(256) fft_kernel(const float* __restrict__ x) {
    __shared__ float2 bufA[NN];
    __shared__ float2 bufB[NN];
    const int row = blockIdx.x;
    const int tid = threadIdx.x;

    const float* xr = x + (size_t)row * NN;
    bufA[tid]       = make_float2(xr[tid], 0.0f);
    bufA[tid + 256] = make_float2(xr[tid + 256], 0.0f);
    __syncthreads();

    float2* X = bufA;
    float2* Y = bufB;
    for (int stage = 0; stage < 9; stage++) {
        const int n = NN >> stage;
        const int m = n >> 1;
        const int s = 1 << stage;
        const int p = tid >> stage;
        const int q = tid & (s - 1);
        float sw, cw;
        __sincosf(-6.283185307179586f * (float)p / (float)n, &sw, &cw);
        const float2 a = X[q + s * p];
        const float2 b = X[q + s * (p + m)];
        Y[q + s * (2 * p)] = make_float2(a.x + b.x, a.y + b.y);
        const float2 dif = make_float2(a.x - b.x, a.y - b.y);
        Y[q + s * (2 * p + 1)] = make_float2(dif.x * cw - dif.y * sw,
                                             dif.x * sw + dif.y * cw);
        __syncthreads();
        float2* t = X; X = Y; Y = t;
    }
    float* gr = g_re + (size_t)row * (2 * NN);
    float* gi = g_im + (size_t)row * (2 * NN);
    for (int i = tid; i < NN; i += 256) {
        const float2 v = X[i];
        gr[i] = v.x; gr[i + NN] = v.x;
        gi[i] = v.y; gi[i + NN] = v.y;
    }
}

// ---------------------------------------------------------------------------
// Kernel 2: bispectrum, upper-triangle 64x64 tiles + Hermitian mirror.
// Bx[k,l] = mean_t y_k conj(y_l) y_{l-k};  Bx[l,k] = conj(Bx[k,l]).
// ---------------------------------------------------------------------------
#define FMA2(d, a, b, c) \
    asm("fma.rn.f32x2 %0, %1, %2, %3;" : "=l"(d) : "l"(a), "l"(b), "l"(c))
#define MUL2(d, a, b) \
    asm("mul.rn.f32x2 %0, %1, %2;" : "=l"(d) : "l"(a), "l"(b))
#define ADD2(d, a, b) \
    asm("add.rn.f32x2 %0, %1, %2;" : "=l"(d) : "l"(a), "l"(b))

__global__ void __launch_bounds__(256, 2) bispec_kernel(float* __restrict__ out) {
    extern __shared__ __align__(16) float smem[];
    float* sWin = smem;                        // [p][s][i]: p*4*WT + s*WT + i
    float* sK   = smem + SMEM_WIN;             // dup float2 tables
    float* sS   = smem + SMEM_WIN + SMEM_KT;   // [c][kk][ll] stride 68

    const int tx  = threadIdx.x;    // 0..7   (l quads)
    const int ky  = threadIdx.y;    // 0..31  (kk mod 32)
    const int tid = ky * 8 + tx;
    const int b   = blockIdx.y;

    // Triangular tile decode: 289-8q is a perfect square at row starts.
    const int qb = blockIdx.x;
    const int ti = (int)((17.0f - sqrtf(289.0f - 8.0f * (float)qb)) * 0.5f
                         + 0.0001f);
    const int tj = ti + qb - ((17 * ti - ti * ti) >> 1);
    const int k0 = ti * TL;
    const int l0 = tj * TL;
    const int baseW = 448 + (tj - ti) * TL;    // C - 64, C = N + l0 - k0
    const bool diag = (ti == tj);

    // ---- window fill: copy_s[p][i] = dup_p[baseW + i + s] ----
    for (int idx = tid; idx < SMEM_WIN; idx += 256) {
        const int p = idx / (4 * WT);
        const int r = idx - p * (4 * WT);
        const int s = r / WT;
        const int i = r - s * WT;
        int src = baseW + i + s;
        if (src > 2 * NN - 1) src = 2 * NN - 1;   // padding, never read
        const float* g = (p & 1) ? g_im : g_re;
        sWin[idx] = g[(size_t)(b * TT + (p >> 1)) * (2 * NN) + src];
    }
    // ---- y_k tables: 0: .25*re dup, 1: .25*im dup, 2: -.25*re dup ----
    for (int idx = tid; idx < 3 * TT * TL; idx += 256) {
        const int which = idx / (TT * TL);
        const int r = idx - which * (TT * TL);    // t*TL + kk
        const float* g = (which == 1) ? g_im : g_re;
        float v = 0.25f * g[(size_t)(b * TT + r / TL) * (2 * NN)
                            + k0 + (r & (TL - 1))];
        if (which == 2) v = -v;
        sK[idx * 2]     = v;
        sK[idx * 2 + 1] = v;
    }

    // ---- persistent y_l registers (2 quads: l = l0+4tx, l0+4tx+32) ----
    ull blr[TT][2][2], bli[TT][2][2];
    #pragma unroll
    for (int t = 0; t < TT; t++) {
        const size_t row = (size_t)(b * TT + t) * (2 * NN);
        #pragma unroll
        for (int h = 0; h < 2; h++) {
            const int l = l0 + 4 * tx + 32 * h;
            const ulonglong2 vr = *(const ulonglong2*)(g_re + row + l);
            const ulonglong2 vi = *(const ulonglong2*)(g_im + row + l);
            blr[t][h][0] = vr.x; blr[t][h][1] = vr.y;
            bli[t][h][0] = vi.x; bli[t][h][1] = vi.y;
        }
    }
    __syncthreads();

    // shift copy s = (4 - kk%4)%4 is thread-fixed (kk = ky + 32*it)
    const int sh = (4 - (ky & 3)) & 3;
    const float* winT = sWin + sh * WT + (64 - ky - sh + 4 * tx);
    const float* kT   = sK + 2 * ky;
    float* outD = out + ((size_t)(b * 2) * NN + (k0 + ky)) * NN + l0 + 4 * tx;
    float* sSt  = sS + ky * 68 + 4 * tx;

    #pragma unroll
    for (int it = 0; it < 2; it++) {            // kk = ky + 32*it
        ull a0[2][2], a1[2][2], a2[2][2], a3[2][2];
        #pragma unroll
        for (int t = 0; t < TT; t++) {
            const ull akr = *(const ull*)(kT + ((0 * TT + t) * TL + 32 * it) * 2);
            const ull aki = *(const ull*)(kT + ((1 * TT + t) * TL + 32 * it) * 2);
            const ull nkr = *(const ull*)(kT + ((2 * TT + t) * TL + 32 * it) * 2);
            #pragma unroll
            for (int h = 0; h < 2; h++) {
                const float* wr = winT + (2 * t + 0) * (4 * WT) + 32 * h - 32 * it;
                const float* wi = winT + (2 * t + 1) * (4 * WT) + 32 * h - 32 * it;
                const ulonglong2 cmr = *(const ulonglong2*)wr;   // LDS.128
                const ulonglong2 cmi = *(const ulonglong2*)wi;   // LDS.128
                #pragma unroll
                for (int q = 0; q < 2; q++) {
                    const ull CR = q ? cmr.y : cmr.x;
                    const ull CI = q ? cmi.y : cmi.x;
                    ull u, v, pr, pi;
                    MUL2(u, aki, bli[t][h][q]);  FMA2(pr, akr, blr[t][h][q], u);
                    MUL2(v, nkr, bli[t][h][q]);  FMA2(pi, aki, blr[t][h][q], v);
                    if (t == 0) {
                        MUL2(a0[h][q], pr, CR); MUL2(a1[h][q], pi, CI);
                        MUL2(a2[h][q], pr, CI); MUL2(a3[h][q], pi, CR);
                    } else {
                        FMA2(a0[h][q], pr, CR, a0[h][q]);
                        FMA2(a1[h][q], pi, CI, a1[h][q]);
                        FMA2(a2[h][q], pr, CI, a2[h][q]);
                        FMA2(a3[h][q], pi, CR, a3[h][q]);
                    }
                }
            }
        }
        // ---- combine + direct store + (off-diag) staging ----
        #pragma unroll
        for (int h = 0; h < 2; h++) {
            ulonglong2 re4, im4;
            const ull n0 = a1[h][0] ^ 0x8000000080000000ULL;
            const ull n1 = a1[h][1] ^ 0x8000000080000000ULL;
            ADD2(re4.x, a0[h][0], n0);
            ADD2(re4.y, a0[h][1], n1);
            ADD2(im4.x, a2[h][0], a3[h][0]);
            ADD2(im4.y, a2[h][1], a3[h][1]);
            *(ulonglong2*)(outD + it * 32 * NN + 32 * h) = re4;
            *(ulonglong2*)(outD + (size_t)NN * NN + it * 32 * NN + 32 * h) = im4;
            if (!diag) {
                *(ulonglong2*)(sSt + (it * 32) * 68 + 32 * h) = re4;
                *(ulonglong2*)(sSt + (TL + it * 32) * 68 + 32 * h) = im4;
            }
        }
    }

    // ---- Hermitian mirror: out[l][k] = conj(Bx[k][l]) ----
    if (!diag) {
        __syncthreads();
        const int r   = tid & 63;   // ll (warp spans 32 distinct banks)
        const int seg = tid >> 6;   // kk chunk of 16
        float* outM = out + ((size_t)(b * 2) * NN + (l0 + r)) * NN
                          + k0 + 16 * seg;
        #pragma unroll
        for (int c = 0; c < 2; c++) {
            float v[16];
            #pragma unroll
            for (int j = 0; j < 16; j++) {
                const float x = sS[(c * TL + 16 * seg + j) * 68 + r];
                v[j] = c ? -x : x;
            }
            #pragma unroll
            for (int qq = 0; qq < 4; qq++)
                *(float4*)(outM + (size_t)c * NN * NN + 4 * qq) =
                    make_float4(v[4 * qq], v[4 * qq + 1],
                                v[4 * qq + 2], v[4 * qq + 3]);
        }
    }
}

// ---------------------------------------------------------------------------
extern "C" void kernel_launch(void* const* d_in, const int* in_sizes, int n_in,
                              void* d_out, int out_size) {
    const float* target = (const float*)d_in[0];
    float* out = (float*)d_out;

    cudaFuncSetAttribute(bispec_kernel,
                         cudaFuncAttributeMaxDynamicSharedMemorySize,
                         SMEM_BYTES);

    fft_kernel<<<NROWS, 256>>>(target);

    dim3 grid(NTILE, BATCH);     // 36 x 32 = 1152 blocks
    dim3 block(8, 32);           // 256 threads
    bispec_kernel<<<grid, block, SMEM_BYTES>>>(out);

    // Second tuple element: passthrough of target, if the harness expects it.
    const long long src_elems = (long long)BATCH * 2 * NN * NN;  // 16,777,216
    if ((long long)out_size > src_elems) {
        const long long tail = (long long)out_size - src_elems;
        cudaMemcpyAsync(out + src_elems, target,
                        (size_t)tail * sizeof(float),
                        cudaMemcpyDeviceToDevice);
    }
}

// round 9
// speedup vs baseline: 1.4818x; 1.4818x over previous
#include <cuda_runtime.h>
#include <cstdint>
#include <cstddef>

typedef unsigned long long ull;

#define BATCH 32
#define TT 4
#define NN 512
#define NROWS (BATCH * TT)  // 128
#define KC 32               // k-values per block
#define WW 544              // window floats per shift copy
#define SMEM_WIN (8 * 4 * WW)           // 17408 floats
#define SMEM_K   (3 * TT * KC * 2)      // 768 floats (dup float2 tables)
#define SMEM_BYTES ((SMEM_WIN + SMEM_K) * 4)   // 72704 B

// FFT results, SoA, duplicated to length 2N so (l-k)%N needs no mod.
__device__ float g_re[NROWS * 2 * NN];
__device__ float g_im[NROWS * 2 * NN];

// ---------------------------------------------------------------------------
// Kernel 1: 512-point complex FFT (Stockham autosort, radix-2), one row/block.
// ---------------------------------------------------------------------------
__global__ void __launch_bounds__(256) fft_kernel(const float* __restrict__ x) {
    __shared__ float2 bufA[NN];
    __shared__ float2 bufB[NN];
    const int row = blockIdx.x;
    const int tid = threadIdx.x;

    const float* xr = x + (size_t)row * NN;
    bufA[tid]       = make_float2(xr[tid], 0.0f);
    bufA[tid + 256] = make_float2(xr[tid + 256], 0.0f);
    __syncthreads();

    float2* X = bufA;
    float2* Y = bufB;
    for (int stage = 0; stage < 9; stage++) {
        const int n = NN >> stage;
        const int m = n >> 1;
        const int s = 1 << stage;
        const int p = tid >> stage;
        const int q = tid & (s - 1);
        float sw, cw;
        __sincosf(-6.283185307179586f * (float)p / (float)n, &sw, &cw);
        const float2 a = X[q + s * p];
        const float2 b = X[q + s * (p + m)];
        Y[q + s * (2 * p)] = make_float2(a.x + b.x, a.y + b.y);
        const float2 dif = make_float2(a.x - b.x, a.y - b.y);
        Y[q + s * (2 * p + 1)] = make_float2(dif.x * cw - dif.y * sw,
                                             dif.x * sw + dif.y * cw);
        __syncthreads();
        float2* t = X; X = Y; Y = t;
    }
    float* gr = g_re + (size_t)row * (2 * NN);
    float* gi = g_im + (size_t)row * (2 * NN);
    for (int i = tid; i < NN; i += 256) {
        const float2 v = X[i];
        gr[i] = v.x; gr[i + NN] = v.x;
        gi[i] = v.y; gi[i + NN] = v.y;
    }
}

// ---------------------------------------------------------------------------
// Kernel 2: bispectrum rows k=0..256 + point-symmetry mirror to rows 257..511.
// Bx[(N-k)%N, (N-l)%N] = conj(Bx[k,l])   (real input).
// ---------------------------------------------------------------------------
#define FMA2(d, a, b, c) \
    asm("fma.rn.f32x2 %0, %1, %2, %3;" : "=l"(d) : "l"(a), "l"(b), "l"(c))
#define MUL2(d, a, b) \
    asm("mul.rn.f32x2 %0, %1, %2;" : "=l"(d) : "l"(a), "l"(b))
#define ADD2(d, a, b) \
    asm("add.rn.f32x2 %0, %1, %2;" : "=l"(d) : "l"(a), "l"(b))

__global__ void __launch_bounds__(256, 2) bispec_kernel(float* __restrict__ out) {
    extern __shared__ __align__(16) float smem[];
    float* sWin = smem;             // [p][s][i] : p*4*WW + s*WW + i
    float* sK   = smem + SMEM_WIN;  // [which][t][kk] dup float2

    const int tx  = threadIdx.x;           // 0..63  (l quads)
    const int ky  = threadIdx.y;           // 0..3   (kk mod 4)
    const int tid = ky * 64 + tx;
    const int b   = blockIdx.y;
    const int k0  = blockIdx.x * KC;       // 0..256
    const int base = NN - k0 - 31;
    const bool nine = (k0 == 256);

    // ---- fill 4-shift window copies: copy_s[p][i] = dup_p[base + i + s] ----
    for (int idx = tid; idx < SMEM_WIN; idx += 256) {
        const int p = idx / (4 * WW);
        const int r = idx - p * (4 * WW);
        const int s = r / WW;
        const int i = r - s * WW;
        int src = base + i + s;
        if (src > 2 * NN - 1) src = 2 * NN - 1;   // unused padding
        const float* g = (p & 1) ? g_im : g_re;
        sWin[idx] = g[(size_t)(b * TT + (p >> 1)) * (2 * NN) + src];
    }
    // ---- y_k tables: 0: .25*re dup, 1: .25*im dup, 2: -.25*re dup ----
    for (int idx = tid; idx < 3 * TT * KC; idx += 256) {
        const int which = idx / (TT * KC);
        const int r = idx - which * (TT * KC);   // t*KC + kk
        const float* g = (which == 1) ? g_im : g_re;
        float v = 0.25f * g[(size_t)(b * TT + r / KC) * (2 * NN) + k0 + (r & (KC - 1))];
        if (which == 2) v = -v;
        sK[idx * 2]     = v;
        sK[idx * 2 + 1] = v;
    }

    // ---- persistent y_l registers: 2 quads x 4t x 2comp x 2 pairs ----
    ull blr[TT][2][2], bli[TT][2][2];
    #pragma unroll
    for (int t = 0; t < TT; t++) {
        const size_t row = (size_t)(b * TT + t) * (2 * NN);
        #pragma unroll
        for (int h = 0; h < 2; h++) {
            const int l = 4 * tx + 256 * h;
            const ulonglong2 vr = *(const ulonglong2*)(g_re + row + l);
            const ulonglong2 vi = *(const ulonglong2*)(g_im + row + l);
            blr[t][h][0] = vr.x; blr[t][h][1] = vr.y;
            bli[t][h][0] = vi.x; bli[t][h][1] = vi.y;
        }
    }
    __syncthreads();

    // thread-fixed shift copy: s = (31-kk)&3 = 3-ky  (kk = 4i+ky)
    const float* winT = sWin + (3 - ky) * WW + 4 * tx + 28;
    const float* kT   = sK + 2 * ky;
    float* outD  = out + ((size_t)(b * 2) * NN + (k0 + ky)) * NN + 4 * tx;
    // Mirror base: row (N - k0 - ky), minus 4i per iteration -> row N - k.
    float* outM0 = out + ((size_t)(b * 2) * NN + (NN - k0 - ky)) * NN;
    const size_t IC = (size_t)NN * NN;

    #pragma unroll
    for (int i = 0; i < 8; i++) {
      if (i == 0 || !nine) {                  // 9th block: only kk=0..3 row set
        ull a0[2][2], a1[2][2], a2[2][2], a3[2][2];  // [h][q] chains
        #pragma unroll
        for (int t = 0; t < TT; t++) {
            const ull akr = *(const ull*)(kT + (0 * TT * KC + t * KC + 4 * i) * 2);
            const ull aki = *(const ull*)(kT + (1 * TT * KC + t * KC + 4 * i) * 2);
            const ull nkr = *(const ull*)(kT + (2 * TT * KC + t * KC + 4 * i) * 2);
            #pragma unroll
            for (int h = 0; h < 2; h++) {
                const float* wr = winT + (2 * t + 0) * 4 * WW + 256 * h - 4 * i;
                const float* wi = winT + (2 * t + 1) * 4 * WW + 256 * h - 4 * i;
                const ulonglong2 cmr = *(const ulonglong2*)wr;  // LDS.128
                const ulonglong2 cmi = *(const ulonglong2*)wi;  // LDS.128
                #pragma unroll
                for (int q = 0; q < 2; q++) {
                    const ull CR = q ? cmr.y : cmr.x;
                    const ull CI = q ? cmi.y : cmi.x;
                    ull u, v, pr, pi;
                    MUL2(u, aki, bli[t][h][q]);  FMA2(pr, akr, blr[t][h][q], u);
                    MUL2(v, nkr, bli[t][h][q]);  FMA2(pi, aki, blr[t][h][q], v);
                    if (t == 0) {
                        MUL2(a0[h][q], pr, CR); MUL2(a1[h][q], pi, CI);
                        MUL2(a2[h][q], pr, CI); MUL2(a3[h][q], pi, CR);
                    } else {
                        FMA2(a0[h][q], pr, CR, a0[h][q]);
                        FMA2(a1[h][q], pi, CI, a1[h][q]);
                        FMA2(a2[h][q], pr, CI, a2[h][q]);
                        FMA2(a3[h][q], pi, CR, a3[h][q]);
                    }
                }
            }
        }
        const bool doDir = !nine || (i == 0 && ky == 0);            // rows 0..256
        const bool doMir = !nine && !(k0 == 0 && i == 0 && ky == 0);
        float* rowM = outM0 - (size_t)(4 * i) * NN;                  // row N-k
        #pragma unroll
        for (int h = 0; h < 2; h++) {
            ulonglong2 re4, im4;
            const ull n0 = a1[h][0] ^ 0x8000000080000000ULL;
            const ull n1 = a1[h][1] ^ 0x8000000080000000ULL;
            ADD2(re4.x, a0[h][0], n0);
            ADD2(re4.y, a0[h][1], n1);
            ADD2(im4.x, a2[h][0], a3[h][0]);
            ADD2(im4.y, a2[h][1], a3[h][1]);
            if (doDir) {
                *(ulonglong2*)(outD + (size_t)(4 * i) * NN + 256 * h) = re4;       // STG.128
                *(ulonglong2*)(outD + IC + (size_t)(4 * i) * NN + 256 * h) = im4;  // STG.128
            }
            if (doMir) {
                const float4 R = *(const float4*)&re4;
                ulonglong2 nim;
                nim.x = im4.x ^ 0x8000000080000000ULL;
                nim.y = im4.y ^ 0x8000000080000000ULL;
                const float4 I = *(const float4*)&nim;
                if (tx == 0 && h == 0) {
                    // l = 0..3 -> cols {0, 511, 510, 509}
                    rowM[0]        = R.x; rowM[511]      = R.y;
                    rowM[510]      = R.z; rowM[509]      = R.w;
                    rowM[IC]       = I.x; rowM[IC + 511] = I.y;
                    rowM[IC + 510] = I.z; rowM[IC + 509] = I.w;
                } else {
                    // l = L..L+3 -> cols (512-L-3)..(512-L), reversed
                    float* p = rowM + (509 - 4 * tx - 256 * h);
                    p[0]      = R.w; p[1]      = R.z; p[2]      = R.y; p[3]      = R.x;
                    p[IC]     = I.w; p[IC + 1] = I.z; p[IC + 2] = I.y; p[IC + 3] = I.x;
                }
            }
        }
      }
    }
}

// ---------------------------------------------------------------------------
extern "C" void kernel_launch(void* const* d_in, const int* in_sizes, int n_in,
                              void* d_out, int out_size) {
    const float* target = (const float*)d_in[0];
    float* out = (float*)d_out;

    cudaFuncSetAttribute(bispec_kernel,
                         cudaFuncAttributeMaxDynamicSharedMemorySize,
                         SMEM_BYTES);

    fft_kernel<<<NROWS, 256>>>(target);

    dim3 grid(9, BATCH);     // k rows 0..255 in 8 blocks + row 256 block
    dim3 block(64, 4);       // 256 threads
    bispec_kernel<<<grid, block, SMEM_BYTES>>>(out);

    // Second tuple element: passthrough of target, if the harness expects it.
    const long long src_elems = (long long)BATCH * 2 * NN * NN;  // 16,777,216
    if ((long long)out_size > src_elems) {
        const long long tail = (long long)out_size - src_elems;
        cudaMemcpyAsync(out + src_elems, target,
                        (size_t)tail * sizeof(float),
                        cudaMemcpyDeviceToDevice);
    }
}